// round 12
// baseline (speedup 1.0000x reference)
#include <cuda_runtime.h>
#include <stdint.h>

#define NN 1000000
#define NE 10000000
#define HID 8
#define NG 64
#define NW 31250

#define CE_IDX 8192
#define CE4    65536
#define CE3    524288
#define CL4    8192
#define CL3    65536
#define CL2    524288
#define BUFE   768

#define NBLK 148
#define TPB  1024
#define NTH  (NBLK * TPB)

// ---- device scratch ----
__device__ int      g_is64;
__device__ int      g_deg[NN];
__device__ float    g_dinv[NN];
__device__ int      g_dstm[NE];           // dst-only stream (40 MB)
__device__ float    g_agg1[NN];
__device__ float    g_agga[NN * HID];
__device__ float    g_aggb[NN * HID];
__device__ float    g_v1[NN * HID];       // g3
__device__ float    g_v2[NN * HID];       // g2 then g4
__device__ unsigned g_bm_idx[NW], g_bm4[NW], g_bm3[NW], g_bm2[NW];
__device__ int2     g_eidx[CE_IDX], g_e4[CE4], g_e3[CE3];
__device__ int      g_l4[CL4], g_l3[CL3], g_l2[CL2];
__device__ int      g_ceidx, g_ce4, g_ce3, g_cl4, g_cl3, g_cl2;

// software grid barrier state (generation-based; safe across graph replays)
__device__ volatile int g_bar_cnt;
__device__ volatile int g_bar_gen;

__device__ __forceinline__ bool bm_test(const unsigned* bm, int i) {
    return (bm[i >> 5] >> (i & 31)) & 1u;
}
__device__ __forceinline__ bool bm_claim(unsigned* bm, int i) {
    unsigned old = atomicOr(&bm[i >> 5], 1u << (i & 31));
    return !((old >> (i & 31)) & 1u);
}
__device__ __forceinline__ int load_src(const void* ei_raw, int e) {
    return g_is64 ? (int)((const long long*)ei_raw)[e]
                  : ((const int*)ei_raw)[e];
}
__device__ __forceinline__ void zero_row(float* p) {
    float4 z = make_float4(0.f, 0.f, 0.f, 0.f);
    ((float4*)p)[0] = z; ((float4*)p)[1] = z;
}

// grid barrier: all NBLK CTAs resident (1/SM) -> spin is deadlock-free
__device__ __forceinline__ void gbar() {
    __syncthreads();
    if (threadIdx.x == 0) {
        int gen = g_bar_gen;
        __threadfence();
        if (atomicAdd((int*)&g_bar_cnt, 1) == NBLK - 1) {
            g_bar_cnt = 0;
            __threadfence();
            g_bar_gen = gen + 1;
        } else {
            while (g_bar_gen == gen) { }
        }
        __threadfence();
    }
    __syncthreads();
}

__global__ void __launch_bounds__(TPB, 1) k_mega(
    const float* __restrict__ x,
    const void* __restrict__ ei,
    const void* __restrict__ idx_raw,
    const float* __restrict__ W1, const float* __restrict__ b1,
    const float* __restrict__ W2, const float* __restrict__ b2,
    const float* __restrict__ W3, const float* __restrict__ b3,
    const float* __restrict__ W4, const float* __restrict__ b4,
    float* __restrict__ out)
{
    const int tid = threadIdx.x;
    const int gid = blockIdx.x * TPB + tid;

    __shared__ int2 s_eb[BUFE];
    __shared__ int  s_nb[BUFE];
    __shared__ int  s_ec, s_nc, s_ebase, s_nbase;

    // ---- ph0: zero state + dtype detect + counter reset ----
    if (gid == 0) {
        const int* w = (const int*)ei;
        int zeros = 0;
        for (int k = 1; k < 128; k += 2)
            if (w[k] == 0) zeros++;
        g_is64 = (zeros >= 48) ? 1 : 0;
        g_ceidx = 0; g_ce4 = 0; g_ce3 = 0;
        g_cl4 = 0; g_cl3 = 0; g_cl2 = 0;
    }
    for (int i = gid; i < NN; i += NTH) g_deg[i] = 0;
    for (int i = gid; i < NW; i += NTH) {
        g_bm_idx[i] = 0; g_bm4[i] = 0; g_bm3[i] = 0; g_bm2[i] = 0;
    }
    gbar();

    // ---- ph1: seed indices into bm_idx / bm4 / l4 ----
    if (gid < NG) {
        int n = g_is64 ? (int)((const long long*)idx_raw)[gid]
                       : ((const int*)idx_raw)[gid];
        bm_claim(g_bm_idx, n);
        if (bm_claim(g_bm4, n)) {
            int p = atomicAdd(&g_cl4, 1);
            if (p < CL4) { g_l4[p] = n; zero_row(g_aggb + (size_t)n * HID); }
        }
    }
    gbar();

    // ---- ph2: p1 — dst stream + degree + E_idx capture + S4 claims ----
    {
        const int NQ = NE / 4;
        const int ITS = (NQ + NTH - 1) / NTH;
        for (int it = 0; it < ITS; it++) {
            if (tid == 0) { s_ec = 0; s_nc = 0; }
            __syncthreads();
            int i = it * NTH + gid;
            if (i < NQ) {
                int d[4];
                if (g_is64) {
                    longlong2 a = ((const longlong2*)ei)[NE / 2 + 2 * i];
                    longlong2 b = ((const longlong2*)ei)[NE / 2 + 2 * i + 1];
                    d[0] = (int)a.x; d[1] = (int)a.y; d[2] = (int)b.x; d[3] = (int)b.y;
                } else {
                    int4 a = ((const int4*)ei)[NE / 4 + i];
                    d[0] = a.x; d[1] = a.y; d[2] = a.z; d[3] = a.w;
                }
                ((int4*)g_dstm)[i] = make_int4(d[0], d[1], d[2], d[3]);
                #pragma unroll
                for (int k = 0; k < 4; k++) atomicAdd(&g_deg[d[k]], 1);
                #pragma unroll
                for (int k = 0; k < 4; k++) {
                    if (bm_test(g_bm_idx, d[k])) {
                        int s = load_src(ei, 4 * i + k);
                        int p = atomicAdd(&s_ec, 1);
                        if (p < BUFE) s_eb[p] = make_int2(s, d[k]);
                        else { int q = atomicAdd(&g_ceidx, 1); if (q < CE_IDX) g_eidx[q] = make_int2(s, d[k]); }
                        if (bm_claim(g_bm4, s)) {
                            int q = atomicAdd(&s_nc, 1);
                            if (q < BUFE) s_nb[q] = s;
                            else { int r = atomicAdd(&g_cl4, 1); if (r < CL4) { g_l4[r] = s; zero_row(g_aggb + (size_t)s * HID); } }
                        }
                    }
                }
            }
            __syncthreads();
            int ec = min(s_ec, BUFE), nc = min(s_nc, BUFE);
            if (tid == 0) {
                s_ebase = ec ? atomicAdd(&g_ceidx, ec) : 0;
                s_nbase = nc ? atomicAdd(&g_cl4, nc) : 0;
            }
            __syncthreads();
            for (int t = tid; t < ec; t += TPB)
                if (s_ebase + t < CE_IDX) g_eidx[s_ebase + t] = s_eb[t];
            for (int t = tid; t < nc; t += TPB)
                if (s_nbase + t < CL4) {
                    int n = s_nb[t];
                    g_l4[s_nbase + t] = n;
                    zero_row(g_aggb + (size_t)n * HID);
                }
            __syncthreads();
        }
    }
    gbar();

    // ---- ph3: dinv + seed l4 -> bm3/l3 ----
    for (int i = gid; i < NN; i += NTH)
        g_dinv[i] = rsqrtf((float)g_deg[i] + 1.0f);
    {
        int c4 = min(g_cl4, CL4);
        for (int i = gid; i < c4; i += NTH) {
            int n = g_l4[i];
            if (bm_claim(g_bm3, n)) {
                int p = atomicAdd(&g_cl3, 1);
                if (p < CL3) { g_l3[p] = n; zero_row(g_agga + (size_t)n * HID); }
            }
        }
    }
    gbar();

    // ---- ph4: scan2 — dst in bm4 -> E4, claim bm3/l3 ----
    {
        const int NO = NE / 8;
        const int ITS = (NO + NTH - 1) / NTH;
        for (int it = 0; it < ITS; it++) {
            if (tid == 0) { s_ec = 0; s_nc = 0; }
            __syncthreads();
            int i = it * NTH + gid;
            if (i < NO) {
                int4 a = ((const int4*)g_dstm)[2 * i];
                int4 b = ((const int4*)g_dstm)[2 * i + 1];
                int ds[8] = {a.x, a.y, a.z, a.w, b.x, b.y, b.z, b.w};
                #pragma unroll
                for (int k = 0; k < 8; k++) {
                    int d = ds[k];
                    if (bm_test(g_bm4, d)) {
                        int s = load_src(ei, 8 * i + k);
                        int p = atomicAdd(&s_ec, 1);
                        if (p < BUFE) s_eb[p] = make_int2(s, d);
                        else { int q = atomicAdd(&g_ce4, 1); if (q < CE4) g_e4[q] = make_int2(s, d); }
                        if (bm_claim(g_bm3, s)) {
                            int q = atomicAdd(&s_nc, 1);
                            if (q < BUFE) s_nb[q] = s;
                            else { int r = atomicAdd(&g_cl3, 1); if (r < CL3) { g_l3[r] = s; zero_row(g_agga + (size_t)s * HID); } }
                        }
                    }
                }
            }
            __syncthreads();
            int ec = min(s_ec, BUFE), nc = min(s_nc, BUFE);
            if (tid == 0) {
                s_ebase = ec ? atomicAdd(&g_ce4, ec) : 0;
                s_nbase = nc ? atomicAdd(&g_cl3, nc) : 0;
            }
            __syncthreads();
            for (int t = tid; t < ec; t += TPB)
                if (s_ebase + t < CE4) g_e4[s_ebase + t] = s_eb[t];
            for (int t = tid; t < nc; t += TPB)
                if (s_nbase + t < CL3) {
                    int n = s_nb[t];
                    g_l3[s_nbase + t] = n;
                    zero_row(g_agga + (size_t)n * HID);
                }
            __syncthreads();
        }
    }
    gbar();

    // ---- ph5: seed l3 -> bm2/l2 ----
    {
        int c3 = min(g_cl3, CL3);
        for (int i = gid; i < c3; i += NTH) {
            int n = g_l3[i];
            if (bm_claim(g_bm2, n)) {
                int p = atomicAdd(&g_cl2, 1);
                if (p < CL2) { g_l2[p] = n; g_agg1[n] = 0.f; }
            }
        }
    }
    gbar();

    // ---- ph6: scan3 — dst in bm3 -> E3, claim bm2/l2 ----
    {
        const int NO = NE / 8;
        const int ITS = (NO + NTH - 1) / NTH;
        for (int it = 0; it < ITS; it++) {
            if (tid == 0) { s_ec = 0; s_nc = 0; }
            __syncthreads();
            int i = it * NTH + gid;
            if (i < NO) {
                int4 a = ((const int4*)g_dstm)[2 * i];
                int4 b = ((const int4*)g_dstm)[2 * i + 1];
                int ds[8] = {a.x, a.y, a.z, a.w, b.x, b.y, b.z, b.w};
                #pragma unroll
                for (int k = 0; k < 8; k++) {
                    int d = ds[k];
                    if (bm_test(g_bm3, d)) {
                        int s = load_src(ei, 8 * i + k);
                        int p = atomicAdd(&s_ec, 1);
                        if (p < BUFE) s_eb[p] = make_int2(s, d);
                        else { int q = atomicAdd(&g_ce3, 1); if (q < CE3) g_e3[q] = make_int2(s, d); }
                        if (bm_claim(g_bm2, s)) {
                            int q = atomicAdd(&s_nc, 1);
                            if (q < BUFE) s_nb[q] = s;
                            else { int r = atomicAdd(&g_cl2, 1); if (r < CL2) { g_l2[r] = s; g_agg1[s] = 0.f; } }
                        }
                    }
                }
            }
            __syncthreads();
            int ec = min(s_ec, BUFE), nc = min(s_nc, BUFE);
            if (tid == 0) {
                s_ebase = ec ? atomicAdd(&g_ce3, ec) : 0;
                s_nbase = nc ? atomicAdd(&g_cl2, nc) : 0;
            }
            __syncthreads();
            for (int t = tid; t < ec; t += TPB)
                if (s_ebase + t < CE3) g_e3[s_ebase + t] = s_eb[t];
            for (int t = tid; t < nc; t += TPB)
                if (s_nbase + t < CL2) {
                    int n = s_nb[t];
                    g_l2[s_nbase + t] = n;
                    g_agg1[n] = 0.f;
                }
            __syncthreads();
        }
    }
    gbar();

    // ---- ph7: p4 — dst in bm2 -> agg1[dst] += x[src]*dinv[src] ----
    {
        const int NO = NE / 8;
        for (int i = gid; i < NO; i += NTH) {
            int4 a = ((const int4*)g_dstm)[2 * i];
            int4 b = ((const int4*)g_dstm)[2 * i + 1];
            int ds[8] = {a.x, a.y, a.z, a.w, b.x, b.y, b.z, b.w};
            #pragma unroll
            for (int k = 0; k < 8; k++) {
                int d = ds[k];
                if (bm_test(g_bm2, d)) {
                    int s = load_src(ei, 8 * i + k);
                    atomicAdd(&g_agg1[d], x[s] * g_dinv[s]);
                }
            }
        }
    }
    gbar();

    // ---- ph8: layer 1+2 at l2 -> v2 ----
    {
        int n2 = min(g_cl2, CL2);
        for (int i = gid; i < n2; i += NTH) {
            int d = g_l2[i];
            float dinv = g_dinv[d];
            float pre = dinv * (g_agg1[d] + x[d] * dinv);
            float h[HID];
            #pragma unroll
            for (int j = 0; j < HID; j++)
                h[j] = fmaxf(pre * __ldg(&W1[j]) + __ldg(&b1[j]), 0.f);
            float* g2 = g_v2 + (size_t)d * HID;
            #pragma unroll
            for (int j = 0; j < HID; j++) {
                float acc = 0.f;
                #pragma unroll
                for (int k = 0; k < HID; k++)
                    acc = fmaf(h[k], __ldg(&W2[k * HID + j]), acc);
                g2[j] = acc * dinv;
            }
        }
    }
    gbar();

    // ---- ph9: eagg3 — agga[dst] += v2[src] over E3 ----
    {
        int ne3 = min(g_ce3, CE3);
        for (int i = gid; i < ne3; i += NTH) {
            int2 sd = g_e3[i];
            const float* gs = g_v2 + (size_t)sd.x * HID;
            float* ad = g_agga + (size_t)sd.y * HID;
            #pragma unroll
            for (int j = 0; j < HID; j++) atomicAdd(ad + j, gs[j]);
        }
    }
    gbar();

    // ---- ph10: node3 at l3 -> v1 ----
    {
        int n3 = min(g_cl3, CL3);
        for (int i = gid; i < n3; i += NTH) {
            int d = g_l3[i];
            float dinv = g_dinv[d];
            const float* gin = g_v2 + (size_t)d * HID;
            const float* ag  = g_agga + (size_t)d * HID;
            float* go        = g_v1 + (size_t)d * HID;
            float h[HID];
            #pragma unroll
            for (int j = 0; j < HID; j++)
                h[j] = fmaxf(dinv * (ag[j] + gin[j]) + __ldg(&b2[j]), 0.f);
            #pragma unroll
            for (int j = 0; j < HID; j++) {
                float acc = 0.f;
                #pragma unroll
                for (int k = 0; k < HID; k++)
                    acc = fmaf(h[k], __ldg(&W3[k * HID + j]), acc);
                go[j] = acc * dinv;
            }
        }
    }
    gbar();

    // ---- ph11: eagg4 — aggb[dst] += v1[src] over E4 ----
    {
        int ne4 = min(g_ce4, CE4);
        for (int i = gid; i < ne4; i += NTH) {
            int2 sd = g_e4[i];
            const float* gs = g_v1 + (size_t)sd.x * HID;
            float* ad = g_aggb + (size_t)sd.y * HID;
            #pragma unroll
            for (int j = 0; j < HID; j++) atomicAdd(ad + j, gs[j]);
        }
    }
    gbar();

    // ---- ph12: node4 at l4 -> v2 ----
    {
        int n4 = min(g_cl4, CL4);
        for (int i = gid; i < n4; i += NTH) {
            int d = g_l4[i];
            float dinv = g_dinv[d];
            const float* gin = g_v1 + (size_t)d * HID;
            const float* ag  = g_aggb + (size_t)d * HID;
            float* go        = g_v2 + (size_t)d * HID;
            float h[HID];
            #pragma unroll
            for (int j = 0; j < HID; j++)
                h[j] = fmaxf(dinv * (ag[j] + gin[j]) + __ldg(&b3[j]), 0.f);
            #pragma unroll
            for (int j = 0; j < HID; j++) {
                float acc = 0.f;
                #pragma unroll
                for (int k = 0; k < HID; k++)
                    acc = fmaf(h[k], __ldg(&W4[k * HID + j]), acc);
                go[j] = acc * dinv;
            }
        }
    }
    gbar();

    // ---- ph13: final gather at indices via E_idx ----
    if (gid < NG) {
        int d = g_is64 ? (int)((const long long*)idx_raw)[gid]
                       : ((const int*)idx_raw)[gid];
        float acc8[HID];
        const float* gd = g_v2 + (size_t)d * HID;
        #pragma unroll
        for (int j = 0; j < HID; j++) acc8[j] = gd[j];
        int n = min(g_ceidx, CE_IDX);
        for (int e = 0; e < n; e++) {
            int2 sd = g_eidx[e];
            if (sd.y == d) {
                const float* gs = g_v2 + (size_t)sd.x * HID;
                #pragma unroll
                for (int j = 0; j < HID; j++) acc8[j] += gs[j];
            }
        }
        float dinv = g_dinv[d];
        #pragma unroll
        for (int j = 0; j < HID; j++)
            out[gid * HID + j] = dinv * acc8[j] + __ldg(&b4[j]);
    }
}

extern "C" void kernel_launch(void* const* d_in, const int* in_sizes, int n_in,
                              void* d_out, int out_size) {
    const float* x  = (const float*)d_in[0];
    const void*  ei = d_in[1];
    const void*  idx = d_in[2];
    const float* W1 = (const float*)d_in[3];
    const float* b1 = (const float*)d_in[4];
    const float* W2 = (const float*)d_in[5];
    const float* b2 = (const float*)d_in[6];
    const float* W3 = (const float*)d_in[7];
    const float* b3 = (const float*)d_in[8];
    const float* W4 = (const float*)d_in[9];
    const float* b4 = (const float*)d_in[10];
    float* out = (float*)d_out;

    k_mega<<<NBLK, TPB>>>(x, ei, idx, W1, b1, W2, b2, W3, b3, W4, b4, out);
}

// round 13
// speedup vs baseline: 1.0930x; 1.0930x over previous
#include <cuda_runtime.h>
#include <stdint.h>

#define NN 1000000
#define NE 10000000
#define HID 8
#define NG 64
#define NW 31250

#define CE_IDX 8192
#define CE4    65536
#define CE3    524288
#define CL4    8192
#define CL3    65536
#define CL2    524288

#define TPB  256
#define CPS  8                 // CTAs per SM
#define NBLK (148 * CPS)       // 1184 co-resident CTAs
#define NTH  (NBLK * TPB)

// ---- device scratch ----
__device__ int      g_is64;
__device__ int      g_deg[NN];
__device__ float    g_dinv[NN];
__device__ int      g_dstm[NE];           // dst-only stream (40 MB)
__device__ float    g_agg1[NN];
__device__ float    g_agga[NN * HID];
__device__ float    g_aggb[NN * HID];
__device__ float    g_v1[NN * HID];       // g3
__device__ float    g_v2[NN * HID];       // g2 then g4
__device__ unsigned g_bm_idx[NW], g_bm4[NW], g_bm3[NW], g_bm2[NW];
__device__ int2     g_eidx[CE_IDX], g_e4[CE4], g_e3[CE3];
__device__ int      g_l4[CL4], g_l3[CL3], g_l2[CL2];
__device__ int      g_ceidx, g_ce4, g_ce3, g_cl4, g_cl3, g_cl2;

// software grid barrier (generation-based; replay-safe)
__device__ volatile int g_bar_cnt;
__device__ volatile int g_bar_gen;

__device__ __forceinline__ bool bm_test(const unsigned* bm, int i) {
    return (bm[i >> 5] >> (i & 31)) & 1u;
}
__device__ __forceinline__ bool bm_claim(unsigned* bm, int i) {
    unsigned old = atomicOr(&bm[i >> 5], 1u << (i & 31));
    return !((old >> (i & 31)) & 1u);
}
__device__ __forceinline__ int load_src(const void* ei_raw, int e) {
    return g_is64 ? (int)((const long long*)ei_raw)[e]
                  : ((const int*)ei_raw)[e];
}
__device__ __forceinline__ void zero_row(float* p) {
    float4 z = make_float4(0.f, 0.f, 0.f, 0.f);
    ((float4*)p)[0] = z; ((float4*)p)[1] = z;
}

// warp-aggregated append: every lane of the warp must call this.
// returns slot index (valid only when hit).
__device__ __forceinline__ int warp_append(int* counter, bool hit) {
    unsigned m = __ballot_sync(0xffffffffu, hit);
    if (!m) return -1;
    int lane = threadIdx.x & 31;
    int leader = __ffs(m) - 1;
    int base = 0;
    if (lane == leader) base = atomicAdd(counter, __popc(m));
    base = __shfl_sync(0xffffffffu, base, leader);
    return base + __popc(m & ((1u << lane) - 1u));
}

// grid barrier: all NBLK CTAs resident (8/SM guaranteed by launch_bounds)
__device__ __forceinline__ void gbar() {
    __syncthreads();
    if (threadIdx.x == 0) {
        int gen = g_bar_gen;
        __threadfence();
        if (atomicAdd((int*)&g_bar_cnt, 1) == NBLK - 1) {
            g_bar_cnt = 0;
            __threadfence();
            g_bar_gen = gen + 1;
        } else {
            while (g_bar_gen == gen) { }
        }
        __threadfence();
    }
    __syncthreads();
}

__global__ void __launch_bounds__(TPB, CPS) k_mega(
    const float* __restrict__ x,
    const void* __restrict__ ei,
    const void* __restrict__ idx_raw,
    const float* __restrict__ W1, const float* __restrict__ b1,
    const float* __restrict__ W2, const float* __restrict__ b2,
    const float* __restrict__ W3, const float* __restrict__ b3,
    const float* __restrict__ W4, const float* __restrict__ b4,
    float* __restrict__ out)
{
    const int gid = blockIdx.x * TPB + threadIdx.x;

    // ---- ph0: zero state + dtype detect ----
    if (gid == 0) {
        const int* w = (const int*)ei;
        int zeros = 0;
        for (int k = 1; k < 128; k += 2)
            if (w[k] == 0) zeros++;
        g_is64 = (zeros >= 48) ? 1 : 0;
        g_ceidx = 0; g_ce4 = 0; g_ce3 = 0;
        g_cl4 = 0; g_cl3 = 0; g_cl2 = 0;
    }
    for (int i = gid; i < NN; i += NTH) g_deg[i] = 0;
    for (int i = gid; i < NW; i += NTH) {
        g_bm_idx[i] = 0; g_bm4[i] = 0; g_bm3[i] = 0; g_bm2[i] = 0;
    }
    gbar();

    // ---- ph1: seed indices into bm_idx / bm4 / l4 ----
    if (gid < NG) {
        int n = g_is64 ? (int)((const long long*)idx_raw)[gid]
                       : ((const int*)idx_raw)[gid];
        bm_claim(g_bm_idx, n);
        if (bm_claim(g_bm4, n)) {
            int p = atomicAdd(&g_cl4, 1);
            if (p < CL4) { g_l4[p] = n; zero_row(g_aggb + (size_t)n * HID); }
        }
    }
    gbar();

    // ---- ph2: p1 — dst stream + degree + E_idx capture + S4 claims ----
    {
        const int NQ = NE / 4;
        const int ITS = (NQ + NTH - 1) / NTH;
        for (int it = 0; it < ITS; it++) {
            int i = it * NTH + gid;
            bool v = (i < NQ);
            int d[4] = {0, 0, 0, 0};
            if (v) {
                if (g_is64) {
                    longlong2 a = ((const longlong2*)ei)[NE / 2 + 2 * i];
                    longlong2 b = ((const longlong2*)ei)[NE / 2 + 2 * i + 1];
                    d[0] = (int)a.x; d[1] = (int)a.y; d[2] = (int)b.x; d[3] = (int)b.y;
                } else {
                    int4 a = ((const int4*)ei)[NE / 4 + i];
                    d[0] = a.x; d[1] = a.y; d[2] = a.z; d[3] = a.w;
                }
                ((int4*)g_dstm)[i] = make_int4(d[0], d[1], d[2], d[3]);
                #pragma unroll
                for (int k = 0; k < 4; k++) atomicAdd(&g_deg[d[k]], 1);
            }
            #pragma unroll
            for (int k = 0; k < 4; k++) {
                bool hit = v && bm_test(g_bm_idx, d[k]);
                int s = 0;
                if (hit) s = load_src(ei, 4 * i + k);
                int pos = warp_append(&g_ceidx, hit);
                if (hit && pos < CE_IDX) g_eidx[pos] = make_int2(s, d[k]);
                bool cl = hit && bm_claim(g_bm4, s);
                int pos2 = warp_append(&g_cl4, cl);
                if (cl && pos2 < CL4) {
                    g_l4[pos2] = s;
                    zero_row(g_aggb + (size_t)s * HID);
                }
            }
        }
    }
    gbar();

    // ---- ph3: dinv + seed l4 -> bm3/l3 ----
    for (int i = gid; i < NN; i += NTH)
        g_dinv[i] = rsqrtf((float)g_deg[i] + 1.0f);
    {
        int c4 = min(g_cl4, CL4);
        for (int i = gid; i < c4; i += NTH) {
            int n = g_l4[i];
            if (bm_claim(g_bm3, n)) {
                int p = atomicAdd(&g_cl3, 1);
                if (p < CL3) { g_l3[p] = n; zero_row(g_agga + (size_t)n * HID); }
            }
        }
    }
    gbar();

    // ---- ph4: scan2 — dst in bm4 -> E4, claim bm3/l3 ----
    {
        const int NO = NE / 8;
        const int ITS = (NO + NTH - 1) / NTH;
        for (int it = 0; it < ITS; it++) {
            int i = it * NTH + gid;
            bool v = (i < NO);
            int ds[8] = {0, 0, 0, 0, 0, 0, 0, 0};
            if (v) {
                int4 a = ((const int4*)g_dstm)[2 * i];
                int4 b = ((const int4*)g_dstm)[2 * i + 1];
                ds[0] = a.x; ds[1] = a.y; ds[2] = a.z; ds[3] = a.w;
                ds[4] = b.x; ds[5] = b.y; ds[6] = b.z; ds[7] = b.w;
            }
            #pragma unroll
            for (int k = 0; k < 8; k++) {
                bool hit = v && bm_test(g_bm4, ds[k]);
                int s = 0;
                if (hit) s = load_src(ei, 8 * i + k);
                int pos = warp_append(&g_ce4, hit);
                if (hit && pos < CE4) g_e4[pos] = make_int2(s, ds[k]);
                bool cl = hit && bm_claim(g_bm3, s);
                int pos2 = warp_append(&g_cl3, cl);
                if (cl && pos2 < CL3) {
                    g_l3[pos2] = s;
                    zero_row(g_agga + (size_t)s * HID);
                }
            }
        }
    }
    gbar();

    // ---- ph5: seed l3 -> bm2/l2 ----
    {
        int c3 = min(g_cl3, CL3);
        for (int i = gid; i < c3; i += NTH) {
            int n = g_l3[i];
            if (bm_claim(g_bm2, n)) {
                int p = atomicAdd(&g_cl2, 1);
                if (p < CL2) { g_l2[p] = n; g_agg1[n] = 0.f; }
            }
        }
    }
    gbar();

    // ---- ph6: scan3 — dst in bm3 -> E3, claim bm2/l2 ----
    {
        const int NO = NE / 8;
        const int ITS = (NO + NTH - 1) / NTH;
        for (int it = 0; it < ITS; it++) {
            int i = it * NTH + gid;
            bool v = (i < NO);
            int ds[8] = {0, 0, 0, 0, 0, 0, 0, 0};
            if (v) {
                int4 a = ((const int4*)g_dstm)[2 * i];
                int4 b = ((const int4*)g_dstm)[2 * i + 1];
                ds[0] = a.x; ds[1] = a.y; ds[2] = a.z; ds[3] = a.w;
                ds[4] = b.x; ds[5] = b.y; ds[6] = b.z; ds[7] = b.w;
            }
            #pragma unroll
            for (int k = 0; k < 8; k++) {
                bool hit = v && bm_test(g_bm3, ds[k]);
                int s = 0;
                if (hit) s = load_src(ei, 8 * i + k);
                int pos = warp_append(&g_ce3, hit);
                if (hit && pos < CE3) g_e3[pos] = make_int2(s, ds[k]);
                bool cl = hit && bm_claim(g_bm2, s);
                int pos2 = warp_append(&g_cl2, cl);
                if (cl && pos2 < CL2) {
                    g_l2[pos2] = s;
                    g_agg1[s] = 0.f;
                }
            }
        }
    }
    gbar();

    // ---- ph7: p4 — dst in bm2 -> agg1[dst] += x[src]*dinv[src] ----
    {
        const int NO = NE / 8;
        for (int i = gid; i < NO; i += NTH) {
            int4 a = ((const int4*)g_dstm)[2 * i];
            int4 b = ((const int4*)g_dstm)[2 * i + 1];
            int ds[8] = {a.x, a.y, a.z, a.w, b.x, b.y, b.z, b.w};
            #pragma unroll
            for (int k = 0; k < 8; k++) {
                int d = ds[k];
                if (bm_test(g_bm2, d)) {
                    int s = load_src(ei, 8 * i + k);
                    atomicAdd(&g_agg1[d], x[s] * g_dinv[s]);
                }
            }
        }
    }
    gbar();

    // ---- ph8: layer 1+2 at l2 -> v2 ----
    {
        int n2 = min(g_cl2, CL2);
        for (int i = gid; i < n2; i += NTH) {
            int d = g_l2[i];
            float dinv = g_dinv[d];
            float pre = dinv * (g_agg1[d] + x[d] * dinv);
            float h[HID];
            #pragma unroll
            for (int j = 0; j < HID; j++)
                h[j] = fmaxf(pre * __ldg(&W1[j]) + __ldg(&b1[j]), 0.f);
            float* g2 = g_v2 + (size_t)d * HID;
            #pragma unroll
            for (int j = 0; j < HID; j++) {
                float acc = 0.f;
                #pragma unroll
                for (int k = 0; k < HID; k++)
                    acc = fmaf(h[k], __ldg(&W2[k * HID + j]), acc);
                g2[j] = acc * dinv;
            }
        }
    }
    gbar();

    // ---- ph9: eagg3 — agga[dst] += v2[src] over E3 ----
    {
        int ne3 = min(g_ce3, CE3);
        for (int i = gid; i < ne3; i += NTH) {
            int2 sd = g_e3[i];
            const float* gs = g_v2 + (size_t)sd.x * HID;
            float* ad = g_agga + (size_t)sd.y * HID;
            #pragma unroll
            for (int j = 0; j < HID; j++) atomicAdd(ad + j, gs[j]);
        }
    }
    gbar();

    // ---- ph10: node3 at l3 -> v1 ----
    {
        int n3 = min(g_cl3, CL3);
        for (int i = gid; i < n3; i += NTH) {
            int d = g_l3[i];
            float dinv = g_dinv[d];
            const float* gin = g_v2 + (size_t)d * HID;
            const float* ag  = g_agga + (size_t)d * HID;
            float* go        = g_v1 + (size_t)d * HID;
            float h[HID];
            #pragma unroll
            for (int j = 0; j < HID; j++)
                h[j] = fmaxf(dinv * (ag[j] + gin[j]) + __ldg(&b2[j]), 0.f);
            #pragma unroll
            for (int j = 0; j < HID; j++) {
                float acc = 0.f;
                #pragma unroll
                for (int k = 0; k < HID; k++)
                    acc = fmaf(h[k], __ldg(&W3[k * HID + j]), acc);
                go[j] = acc * dinv;
            }
        }
    }
    gbar();

    // ---- ph11: eagg4 — aggb[dst] += v1[src] over E4 ----
    {
        int ne4 = min(g_ce4, CE4);
        for (int i = gid; i < ne4; i += NTH) {
            int2 sd = g_e4[i];
            const float* gs = g_v1 + (size_t)sd.x * HID;
            float* ad = g_aggb + (size_t)sd.y * HID;
            #pragma unroll
            for (int j = 0; j < HID; j++) atomicAdd(ad + j, gs[j]);
        }
    }
    gbar();

    // ---- ph12: node4 at l4 -> v2 ----
    {
        int n4 = min(g_cl4, CL4);
        for (int i = gid; i < n4; i += NTH) {
            int d = g_l4[i];
            float dinv = g_dinv[d];
            const float* gin = g_v1 + (size_t)d * HID;
            const float* ag  = g_aggb + (size_t)d * HID;
            float* go        = g_v2 + (size_t)d * HID;
            float h[HID];
            #pragma unroll
            for (int j = 0; j < HID; j++)
                h[j] = fmaxf(dinv * (ag[j] + gin[j]) + __ldg(&b3[j]), 0.f);
            #pragma unroll
            for (int j = 0; j < HID; j++) {
                float acc = 0.f;
                #pragma unroll
                for (int k = 0; k < HID; k++)
                    acc = fmaf(h[k], __ldg(&W4[k * HID + j]), acc);
                go[j] = acc * dinv;
            }
        }
    }
    gbar();

    // ---- ph13: final gather at indices via E_idx ----
    if (gid < NG) {
        int d = g_is64 ? (int)((const long long*)idx_raw)[gid]
                       : ((const int*)idx_raw)[gid];
        float acc8[HID];
        const float* gd = g_v2 + (size_t)d * HID;
        #pragma unroll
        for (int j = 0; j < HID; j++) acc8[j] = gd[j];
        int n = min(g_ceidx, CE_IDX);
        for (int e = 0; e < n; e++) {
            int2 sd = g_eidx[e];
            if (sd.y == d) {
                const float* gs = g_v2 + (size_t)sd.x * HID;
                #pragma unroll
                for (int j = 0; j < HID; j++) acc8[j] += gs[j];
            }
        }
        float dinv = g_dinv[d];
        #pragma unroll
        for (int j = 0; j < HID; j++)
            out[gid * HID + j] = dinv * acc8[j] + __ldg(&b4[j]);
    }
}

extern "C" void kernel_launch(void* const* d_in, const int* in_sizes, int n_in,
                              void* d_out, int out_size) {
    const float* x  = (const float*)d_in[0];
    const void*  ei = d_in[1];
    const void*  idx = d_in[2];
    const float* W1 = (const float*)d_in[3];
    const float* b1 = (const float*)d_in[4];
    const float* W2 = (const float*)d_in[5];
    const float* b2 = (const float*)d_in[6];
    const float* W3 = (const float*)d_in[7];
    const float* b3 = (const float*)d_in[8];
    const float* W4 = (const float*)d_in[9];
    const float* b4 = (const float*)d_in[10];
    float* out = (float*)d_out;

    k_mega<<<NBLK, TPB>>>(x, ei, idx, W1, b1, W2, b2, W3, b3, W4, b4, out);
}

// round 14
// speedup vs baseline: 1.2226x; 1.1185x over previous
#include <cuda_runtime.h>
#include <stdint.h>

#define NN 1000000
#define NE 10000000
#define HID 8
#define NG 64
#define NW 31250

#define CE_IDX 8192
#define CE4    65536
#define CE3    524288
#define CL4    8192
#define CL3    65536
#define CL2    524288
#define BUF    256

#define NB_NODE 3907            // ceil(NN/256)
#define NB_L4   (CL4/256)
#define NB_L3   (CL3/256)
#define NT_P1   625000          // NE/16 threads
#define NB_P1   2442            // ceil(625000/256)
#define NT_SC   312500          // NE/32 threads
#define NB_SC   1221            // ceil(312500/256)

// ---- device scratch ----
__device__ int      g_is64;
__device__ int      g_deg[NN];
__device__ float    g_dinv[NN];
__device__ int      g_dstm[NE];           // dst-only stream (40 MB)
__device__ float    g_agg1[NN];
__device__ float    g_agga[NN * HID];
__device__ float    g_aggb[NN * HID];
__device__ float    g_v1[NN * HID];       // g3
__device__ float    g_v2[NN * HID];       // g2 then g4
__device__ unsigned g_bm_idx[NW], g_bm4[NW], g_bm3[NW], g_bm2[NW];
__device__ int2     g_eidx[CE_IDX], g_e4[CE4], g_e3[CE3];
__device__ int      g_l4[CL4], g_l3[CL3], g_l2[CL2];
__device__ int      g_ceidx, g_ce4, g_ce3, g_cl4, g_cl3, g_cl2;

__device__ __forceinline__ bool bm_test(const unsigned* bm, int i) {
    return (bm[i >> 5] >> (i & 31)) & 1u;
}
__device__ __forceinline__ bool bm_claim(unsigned* bm, int i) {
    unsigned old = atomicOr(&bm[i >> 5], 1u << (i & 31));
    return !((old >> (i & 31)) & 1u);
}
__device__ __forceinline__ int load_src(const void* ei_raw, int e) {
    return g_is64 ? (int)((const long long*)ei_raw)[e]
                  : ((const int*)ei_raw)[e];
}
__device__ __forceinline__ void zero_row(float* p) {
    float4 z = make_float4(0.f, 0.f, 0.f, 0.f);
    ((float4*)p)[0] = z; ((float4*)p)[1] = z;
}

// init + dtype detect
__global__ void k_init(const void* __restrict__ ei_raw) {
    int i = blockIdx.x * blockDim.x + threadIdx.x;
    int stride = gridDim.x * blockDim.x;
    if (blockIdx.x == 0 && threadIdx.x == 0) {
        const int* w = (const int*)ei_raw;
        int zeros = 0;
        for (int k = 1; k < 128; k += 2)
            if (w[k] == 0) zeros++;
        g_is64 = (zeros >= 48) ? 1 : 0;
        g_ceidx = 0; g_ce4 = 0; g_ce3 = 0;
        g_cl4 = 0; g_cl3 = 0; g_cl2 = 0;
    }
    for (int k = i; k < NN; k += stride) g_deg[k] = 0;
    for (int k = i; k < NW; k += stride) {
        g_bm_idx[k] = 0; g_bm4[k] = 0; g_bm3[k] = 0; g_bm2[k] = 0;
    }
}

__global__ void k_seed0(const void* __restrict__ idx_raw) {
    int k = threadIdx.x;
    if (k >= NG) return;
    int n = g_is64 ? (int)((const long long*)idx_raw)[k]
                   : ((const int*)idx_raw)[k];
    bm_claim(g_bm_idx, n);
    if (bm_claim(g_bm4, n)) {
        int p = atomicAdd(&g_cl4, 1);
        g_l4[p] = n;
        zero_row(g_aggb + (size_t)n * HID);
    }
}

// P1: 16 edges/thread, front-batched loads (MLP 8); dst stream + deg + captures
__global__ void k_p1(const void* __restrict__ ei_raw) {
    __shared__ int2 ebuf[BUF];
    __shared__ int  nbuf[BUF];
    __shared__ int  ecnt, ncnt, ebase, nbase;
    if (threadIdx.x == 0) { ecnt = 0; ncnt = 0; }
    __syncthreads();
    int i = blockIdx.x * blockDim.x + threadIdx.x;   // 16-edge chunk index
    if (i < NT_P1) {
        int d[16];
        if (g_is64) {
            longlong2 t[8];
            const longlong2* dp = (const longlong2*)ei_raw + NE / 2 + (size_t)i * 8;
            #pragma unroll
            for (int j = 0; j < 8; j++) t[j] = dp[j];
            #pragma unroll
            for (int j = 0; j < 8; j++) { d[2 * j] = (int)t[j].x; d[2 * j + 1] = (int)t[j].y; }
        } else {
            int4 t[4];
            const int4* dp = (const int4*)ei_raw + NE / 4 + (size_t)i * 4;
            #pragma unroll
            for (int j = 0; j < 4; j++) t[j] = dp[j];
            #pragma unroll
            for (int j = 0; j < 4; j++) {
                d[4 * j] = t[j].x; d[4 * j + 1] = t[j].y;
                d[4 * j + 2] = t[j].z; d[4 * j + 3] = t[j].w;
            }
        }
        int4* outp = (int4*)g_dstm + (size_t)i * 4;
        #pragma unroll
        for (int j = 0; j < 4; j++)
            outp[j] = make_int4(d[4 * j], d[4 * j + 1], d[4 * j + 2], d[4 * j + 3]);
        #pragma unroll
        for (int k = 0; k < 16; k++) atomicAdd(&g_deg[d[k]], 1);
        #pragma unroll
        for (int k = 0; k < 16; k++) {
            if (bm_test(g_bm_idx, d[k])) {
                int s = load_src(ei_raw, 16 * i + k);
                int p = atomicAdd(&ecnt, 1);
                if (p < BUF) ebuf[p] = make_int2(s, d[k]);
                else { int q = atomicAdd(&g_ceidx, 1); if (q < CE_IDX) g_eidx[q] = make_int2(s, d[k]); }
                if (bm_claim(g_bm4, s)) {
                    int q = atomicAdd(&ncnt, 1);
                    if (q < BUF) nbuf[q] = s;
                    else { int r = atomicAdd(&g_cl4, 1); if (r < CL4) { g_l4[r] = s; zero_row(g_aggb + (size_t)s * HID); } }
                }
            }
        }
    }
    __syncthreads();
    int ec = min(ecnt, BUF), nc = min(ncnt, BUF);
    if (threadIdx.x == 0) {
        ebase = ec ? atomicAdd(&g_ceidx, ec) : 0;
        nbase = nc ? atomicAdd(&g_cl4, nc) : 0;
    }
    __syncthreads();
    for (int t = threadIdx.x; t < ec; t += blockDim.x)
        if (ebase + t < CE_IDX) g_eidx[ebase + t] = ebuf[t];
    for (int t = threadIdx.x; t < nc; t += blockDim.x)
        if (nbase + t < CL4) {
            int n = nbuf[t];
            g_l4[nbase + t] = n;
            zero_row(g_aggb + (size_t)n * HID);
        }
}

// fused stage-2: scan blocks (32 edges/thread, MLP 8): dst in bm4 -> E4, claim bm3
//                extra blocks: dinv ; seed l4 -> bm3/l3
__global__ void k_scan2f(const void* __restrict__ ei_raw) {
    if (blockIdx.x >= NB_SC) {
        int rb = blockIdx.x - NB_SC;
        if (rb < NB_NODE) {
            int n = rb * blockDim.x + threadIdx.x;
            if (n < NN) g_dinv[n] = rsqrtf((float)g_deg[n] + 1.0f);
        } else {
            int j = (rb - NB_NODE) * blockDim.x + threadIdx.x;
            if (j < min(g_cl4, CL4)) {
                int n = g_l4[j];
                if (bm_claim(g_bm3, n)) {
                    int p = atomicAdd(&g_cl3, 1);
                    if (p < CL3) { g_l3[p] = n; zero_row(g_agga + (size_t)n * HID); }
                }
            }
        }
        return;
    }
    __shared__ int2 ebuf[BUF];
    __shared__ int  nbuf[BUF];
    __shared__ int  ecnt, ncnt, ebase, nbase;
    if (threadIdx.x == 0) { ecnt = 0; ncnt = 0; }
    __syncthreads();
    int i = blockIdx.x * blockDim.x + threadIdx.x;   // 32-edge chunk index
    if (i < NT_SC) {
        int4 q[8];
        const int4* dp = (const int4*)g_dstm + (size_t)i * 8;
        #pragma unroll
        for (int j = 0; j < 8; j++) q[j] = dp[j];
        #pragma unroll
        for (int j = 0; j < 8; j++) {
            int ds[4] = {q[j].x, q[j].y, q[j].z, q[j].w};
            #pragma unroll
            for (int k = 0; k < 4; k++) {
                int d = ds[k];
                if (bm_test(g_bm4, d)) {
                    int s = load_src(ei_raw, 32 * i + 4 * j + k);
                    int p = atomicAdd(&ecnt, 1);
                    if (p < BUF) ebuf[p] = make_int2(s, d);
                    else { int qq = atomicAdd(&g_ce4, 1); if (qq < CE4) g_e4[qq] = make_int2(s, d); }
                    if (bm_claim(g_bm3, s)) {
                        int qq = atomicAdd(&ncnt, 1);
                        if (qq < BUF) nbuf[qq] = s;
                        else { int r = atomicAdd(&g_cl3, 1); if (r < CL3) { g_l3[r] = s; zero_row(g_agga + (size_t)s * HID); } }
                    }
                }
            }
        }
    }
    __syncthreads();
    int ec = min(ecnt, BUF), nc = min(ncnt, BUF);
    if (threadIdx.x == 0) {
        ebase = ec ? atomicAdd(&g_ce4, ec) : 0;
        nbase = nc ? atomicAdd(&g_cl3, nc) : 0;
    }
    __syncthreads();
    for (int t = threadIdx.x; t < ec; t += blockDim.x)
        if (ebase + t < CE4) g_e4[ebase + t] = ebuf[t];
    for (int t = threadIdx.x; t < nc; t += blockDim.x)
        if (nbase + t < CL3) {
            int n = nbuf[t];
            g_l3[nbase + t] = n;
            zero_row(g_agga + (size_t)n * HID);
        }
}

// fused stage-3: scan blocks (32 edges/thread): dst in bm3 -> E3, claim bm2
//                extra blocks: seed l3 -> bm2/l2
__global__ void k_scan3f(const void* __restrict__ ei_raw) {
    if (blockIdx.x >= NB_SC) {
        int j = (blockIdx.x - NB_SC) * blockDim.x + threadIdx.x;
        if (j < min(g_cl3, CL3)) {
            int n = g_l3[j];
            if (bm_claim(g_bm2, n)) {
                int p = atomicAdd(&g_cl2, 1);
                if (p < CL2) { g_l2[p] = n; g_agg1[n] = 0.f; }
            }
        }
        return;
    }
    __shared__ int2 ebuf[BUF];
    __shared__ int  nbuf[BUF];
    __shared__ int  ecnt, ncnt, ebase, nbase;
    if (threadIdx.x == 0) { ecnt = 0; ncnt = 0; }
    __syncthreads();
    int i = blockIdx.x * blockDim.x + threadIdx.x;
    if (i < NT_SC) {
        int4 q[8];
        const int4* dp = (const int4*)g_dstm + (size_t)i * 8;
        #pragma unroll
        for (int j = 0; j < 8; j++) q[j] = dp[j];
        #pragma unroll
        for (int j = 0; j < 8; j++) {
            int ds[4] = {q[j].x, q[j].y, q[j].z, q[j].w};
            #pragma unroll
            for (int k = 0; k < 4; k++) {
                int d = ds[k];
                if (bm_test(g_bm3, d)) {
                    int s = load_src(ei_raw, 32 * i + 4 * j + k);
                    int p = atomicAdd(&ecnt, 1);
                    if (p < BUF) ebuf[p] = make_int2(s, d);
                    else { int qq = atomicAdd(&g_ce3, 1); if (qq < CE3) g_e3[qq] = make_int2(s, d); }
                    if (bm_claim(g_bm2, s)) {
                        int qq = atomicAdd(&ncnt, 1);
                        if (qq < BUF) nbuf[qq] = s;
                        else { int r = atomicAdd(&g_cl2, 1); if (r < CL2) { g_l2[r] = s; g_agg1[s] = 0.f; } }
                    }
                }
            }
        }
    }
    __syncthreads();
    int ec = min(ecnt, BUF), nc = min(ncnt, BUF);
    if (threadIdx.x == 0) {
        ebase = ec ? atomicAdd(&g_ce3, ec) : 0;
        nbase = nc ? atomicAdd(&g_cl2, nc) : 0;
    }
    __syncthreads();
    for (int t = threadIdx.x; t < ec; t += blockDim.x)
        if (ebase + t < CE3) g_e3[ebase + t] = ebuf[t];
    for (int t = threadIdx.x; t < nc; t += blockDim.x)
        if (nbase + t < CL2) {
            int n = nbuf[t];
            g_l2[nbase + t] = n;
            g_agg1[n] = 0.f;
        }
}

// P4: 32 edges/thread, batched loads; dst in bm2 -> agg1[dst] += x[src]*dinv[src]
__global__ void k_p4(const void* __restrict__ ei_raw, const float* __restrict__ x) {
    int i = blockIdx.x * blockDim.x + threadIdx.x;
    if (i >= NT_SC) return;
    int4 q[8];
    const int4* dp = (const int4*)g_dstm + (size_t)i * 8;
    #pragma unroll
    for (int j = 0; j < 8; j++) q[j] = dp[j];
    #pragma unroll
    for (int j = 0; j < 8; j++) {
        int ds[4] = {q[j].x, q[j].y, q[j].z, q[j].w};
        #pragma unroll
        for (int k = 0; k < 4; k++) {
            int d = ds[k];
            if (bm_test(g_bm2, d)) {
                int s = load_src(ei_raw, 32 * i + 4 * j + k);
                atomicAdd(&g_agg1[d], x[s] * g_dinv[s]);
            }
        }
    }
}

// layer 1+2 at S2: g2 = (relu(dinv*(agg1 + x*dinv)*W1 + b1) @ W2) * dinv -> v2
__global__ void k_layer2(const float* __restrict__ x,
                         const float* __restrict__ W1,
                         const float* __restrict__ b1,
                         const float* __restrict__ W2) {
    int i = blockIdx.x * blockDim.x + threadIdx.x;
    if (i >= min(g_cl2, CL2)) return;
    int d = g_l2[i];
    float dinv = g_dinv[d];
    float pre = dinv * (g_agg1[d] + x[d] * dinv);
    float h[HID];
    #pragma unroll
    for (int j = 0; j < HID; j++)
        h[j] = fmaxf(pre * __ldg(&W1[j]) + __ldg(&b1[j]), 0.f);
    float* g2 = g_v2 + (size_t)d * HID;
    #pragma unroll
    for (int j = 0; j < HID; j++) {
        float acc = 0.f;
        #pragma unroll
        for (int k = 0; k < HID; k++)
            acc = fmaf(h[k], __ldg(&W2[k * HID + j]), acc);
        g2[j] = acc * dinv;
    }
}

// edge-list aggregate: agg[dst] += gsrc[src]
__global__ void k_eagg(int which) {   // 3: E3/v2->agga ; 4: E4/v1->aggb
    int i = blockIdx.x * blockDim.x + threadIdx.x;
    int n = (which == 3) ? min(g_ce3, CE3) : min(g_ce4, CE4);
    if (i >= n) return;
    int2 sd = (which == 3) ? g_e3[i] : g_e4[i];
    const float* gs = ((which == 3) ? g_v2 : g_v1) + (size_t)sd.x * HID;
    float* ad = ((which == 3) ? g_agga : g_aggb) + (size_t)sd.y * HID;
    #pragma unroll
    for (int j = 0; j < HID; j++) atomicAdd(ad + j, gs[j]);
}

// node transform
__global__ void k_node(int which,
                       const float* __restrict__ W,
                       const float* __restrict__ b) {
    int i = blockIdx.x * blockDim.x + threadIdx.x;
    int n = (which == 3) ? min(g_cl3, CL3) : min(g_cl4, CL4);
    if (i >= n) return;
    int d = (which == 3) ? g_l3[i] : g_l4[i];
    const float* gin = ((which == 3) ? g_v2 : g_v1) + (size_t)d * HID;
    const float* ag  = ((which == 3) ? g_agga : g_aggb) + (size_t)d * HID;
    float* gout      = ((which == 3) ? g_v1 : g_v2) + (size_t)d * HID;
    float dinv = g_dinv[d];
    float h[HID];
    #pragma unroll
    for (int j = 0; j < HID; j++)
        h[j] = fmaxf(dinv * (ag[j] + gin[j]) + __ldg(&b[j]), 0.f);
    #pragma unroll
    for (int j = 0; j < HID; j++) {
        float a = 0.f;
        #pragma unroll
        for (int k = 0; k < HID; k++)
            a = fmaf(h[k], __ldg(&W[k * HID + j]), a);
        gout[j] = a * dinv;
    }
}

// final gather
__global__ void k_final(const void* __restrict__ idx_raw,
                        const float* __restrict__ b4,
                        float* __restrict__ out) {
    int k = threadIdx.x;
    if (k >= NG) return;
    int d = g_is64 ? (int)((const long long*)idx_raw)[k]
                   : ((const int*)idx_raw)[k];
    float acc8[HID];
    const float* gd = g_v2 + (size_t)d * HID;
    #pragma unroll
    for (int j = 0; j < HID; j++) acc8[j] = gd[j];
    int n = min(g_ceidx, CE_IDX);
    for (int e = 0; e < n; e++) {
        int2 sd = g_eidx[e];
        if (sd.y == d) {
            const float* gs = g_v2 + (size_t)sd.x * HID;
            #pragma unroll
            for (int j = 0; j < HID; j++) acc8[j] += gs[j];
        }
    }
    float dinv = g_dinv[d];
    #pragma unroll
    for (int j = 0; j < HID; j++)
        out[k * HID + j] = dinv * acc8[j] + __ldg(&b4[j]);
}

extern "C" void kernel_launch(void* const* d_in, const int* in_sizes, int n_in,
                              void* d_out, int out_size) {
    const float* x  = (const float*)d_in[0];
    const void*  ei = d_in[1];
    const void*  idx = d_in[2];
    const float* W1 = (const float*)d_in[3];
    const float* b1 = (const float*)d_in[4];
    const float* W2 = (const float*)d_in[5];
    const float* b2 = (const float*)d_in[6];
    const float* W3 = (const float*)d_in[7];
    const float* b3 = (const float*)d_in[8];
    const float* W4 = (const float*)d_in[9];
    const float* b4 = (const float*)d_in[10];
    float* out = (float*)d_out;

    const int TB = 256;

    k_init<<<1024, TB>>>(ei);
    k_seed0<<<1, 64>>>(idx);
    k_p1<<<NB_P1, TB>>>(ei);
    k_scan2f<<<NB_SC + NB_NODE + NB_L4, TB>>>(ei);
    k_scan3f<<<NB_SC + NB_L3, TB>>>(ei);
    k_p4<<<NB_SC, TB>>>(ei, x);
    k_layer2<<<CL2 / TB, TB>>>(x, W1, b1, W2);
    k_eagg<<<CE3 / TB, TB>>>(3);
    k_node<<<CL3 / TB, TB>>>(3, W3, b2);
    k_eagg<<<CE4 / TB, TB>>>(4);
    k_node<<<CL4 / TB, TB>>>(4, W4, b3);
    k_final<<<1, 64>>>(idx, b4, out);
}

// round 15
// speedup vs baseline: 1.4599x; 1.1941x over previous
#include <cuda_runtime.h>
#include <stdint.h>

#define NN 1000000
#define NE 10000000
#define HID 8
#define NG 64
#define NW 31250

#define CE_IDX 8192
#define CE4    65536
#define CE3    524288
#define CL4    8192
#define CL3    65536
#define CL2    524288
#define BUF    256

#define NB_SCAN 4883            // ceil((NE/8)/256)
#define NB_NODE 3907            // ceil(NN/256)
#define NB_L4   (CL4/256)
#define NB_L3   (CL3/256)
#define NB_BM   123             // ceil(NW/256)

// ---- device scratch (zero-initialized at load; self-cleaned each run) ----
__device__ int      g_is64;
__device__ int      g_deg[NN];
__device__ float    g_dinv[NN];
__device__ float    g_xd[NN];             // x * dinv
__device__ int      g_dstm[NE];           // dst-only stream (40 MB)
__device__ float    g_agg1[NN];
__device__ float    g_agga[NN * HID];
__device__ float    g_aggb[NN * HID];
__device__ float    g_v1[NN * HID];       // g3
__device__ float    g_v2[NN * HID];       // g2 then g4
__device__ unsigned g_bm_idx[NW], g_bm4[NW], g_bm3[NW], g_bm2[NW];
__device__ int2     g_eidx[CE_IDX], g_e4[CE4], g_e3[CE3];
__device__ int      g_l4[CL4], g_l3[CL3], g_l2[CL2];
__device__ int      g_ceidx, g_ce4, g_ce3, g_cl4, g_cl3, g_cl2;

__device__ __forceinline__ bool bm_test(const unsigned* bm, int i) {
    return (bm[i >> 5] >> (i & 31)) & 1u;
}
__device__ __forceinline__ bool bm_claim(unsigned* bm, int i) {
    unsigned old = atomicOr(&bm[i >> 5], 1u << (i & 31));
    return !((old >> (i & 31)) & 1u);
}
__device__ __forceinline__ int load_src(const void* ei_raw, int e) {
    return g_is64 ? (int)((const long long*)ei_raw)[e]
                  : ((const int*)ei_raw)[e];
}
__device__ __forceinline__ void zero_row(float* p) {
    float4 z = make_float4(0.f, 0.f, 0.f, 0.f);
    ((float4*)p)[0] = z; ((float4*)p)[1] = z;
}

// seed: dtype detect (thread 0) then mark indices. bitmaps/counters are zeroed
// (module load on run 1; self-cleaning on later runs).
__global__ void k_seed0(const void* __restrict__ ei_raw,
                        const void* __restrict__ idx_raw) {
    __shared__ int s64;
    if (threadIdx.x == 0) {
        const int* w = (const int*)ei_raw;
        int zeros = 0;
        for (int k = 1; k < 128; k += 2)
            if (w[k] == 0) zeros++;
        s64 = (zeros >= 48) ? 1 : 0;
        g_is64 = s64;
    }
    __syncthreads();
    int k = threadIdx.x;
    if (k >= NG) return;
    int n = s64 ? (int)((const long long*)idx_raw)[k]
                : ((const int*)idx_raw)[k];
    bm_claim(g_bm_idx, n);
    if (bm_claim(g_bm4, n)) {
        int p = atomicAdd(&g_cl4, 1);
        g_l4[p] = n;
        zero_row(g_aggb + (size_t)n * HID);
    }
}

// P1: 4 edges/thread; write dst32, degree REDG, capture dst-in-idx + S4
__global__ void k_p1(const void* __restrict__ ei_raw) {
    __shared__ int2 ebuf[BUF];
    __shared__ int  nbuf[BUF];
    __shared__ int  ecnt, ncnt, ebase, nbase;
    if (threadIdx.x == 0) { ecnt = 0; ncnt = 0; }
    __syncthreads();
    int i = blockIdx.x * blockDim.x + threadIdx.x;   // edge-quad index
    if (i < NE / 4) {
        int d[4];
        if (g_is64) {
            longlong2 a = ((const longlong2*)ei_raw)[NE / 2 + 2 * i];
            longlong2 b = ((const longlong2*)ei_raw)[NE / 2 + 2 * i + 1];
            d[0] = (int)a.x; d[1] = (int)a.y; d[2] = (int)b.x; d[3] = (int)b.y;
        } else {
            int4 a = ((const int4*)ei_raw)[NE / 4 + i];
            d[0] = a.x; d[1] = a.y; d[2] = a.z; d[3] = a.w;
        }
        ((int4*)g_dstm)[i] = make_int4(d[0], d[1], d[2], d[3]);
        #pragma unroll
        for (int k = 0; k < 4; k++) atomicAdd(&g_deg[d[k]], 1);
        #pragma unroll
        for (int k = 0; k < 4; k++) {
            if (bm_test(g_bm_idx, d[k])) {
                int s = load_src(ei_raw, 4 * i + k);
                int p = atomicAdd(&ecnt, 1);
                if (p < BUF) ebuf[p] = make_int2(s, d[k]);
                else { int q = atomicAdd(&g_ceidx, 1); if (q < CE_IDX) g_eidx[q] = make_int2(s, d[k]); }
                if (bm_claim(g_bm4, s)) {
                    int q = atomicAdd(&ncnt, 1);
                    if (q < BUF) nbuf[q] = s;
                    else { int r = atomicAdd(&g_cl4, 1); if (r < CL4) { g_l4[r] = s; zero_row(g_aggb + (size_t)s * HID); } }
                }
            }
        }
    }
    __syncthreads();
    int ec = min(ecnt, BUF), nc = min(ncnt, BUF);
    if (threadIdx.x == 0) {
        ebase = ec ? atomicAdd(&g_ceidx, ec) : 0;
        nbase = nc ? atomicAdd(&g_cl4, nc) : 0;
    }
    __syncthreads();
    for (int t = threadIdx.x; t < ec; t += blockDim.x)
        if (ebase + t < CE_IDX) g_eidx[ebase + t] = ebuf[t];
    for (int t = threadIdx.x; t < nc; t += blockDim.x)
        if (nbase + t < CL4) {
            int n = nbuf[t];
            g_l4[nbase + t] = n;
            zero_row(g_aggb + (size_t)n * HID);
        }
}

// fused stage-2: scan blocks (8 edges/thread): dst in bm4 -> E4, claim bm3
//                extra blocks: dinv+xd ; seed l4 -> bm3/l3
__global__ void k_scan2f(const void* __restrict__ ei_raw,
                         const float* __restrict__ x) {
    if (blockIdx.x >= NB_SCAN) {
        int rb = blockIdx.x - NB_SCAN;
        if (rb < NB_NODE) {
            int n = rb * blockDim.x + threadIdx.x;
            if (n < NN) {
                float dinv = rsqrtf((float)g_deg[n] + 1.0f);
                g_dinv[n] = dinv;
                g_xd[n] = x[n] * dinv;
            }
        } else {
            int j = (rb - NB_NODE) * blockDim.x + threadIdx.x;
            if (j < min(g_cl4, CL4)) {
                int n = g_l4[j];
                if (bm_claim(g_bm3, n)) {
                    int p = atomicAdd(&g_cl3, 1);
                    if (p < CL3) { g_l3[p] = n; zero_row(g_agga + (size_t)n * HID); }
                }
            }
        }
        return;
    }
    __shared__ int2 ebuf[BUF];
    __shared__ int  nbuf[BUF];
    __shared__ int  ecnt, ncnt, ebase, nbase;
    if (threadIdx.x == 0) { ecnt = 0; ncnt = 0; }
    __syncthreads();
    int i = blockIdx.x * blockDim.x + threadIdx.x;   // edge-oct index
    if (i < NE / 8) {
        int4 a = ((const int4*)g_dstm)[2 * i];
        int4 b = ((const int4*)g_dstm)[2 * i + 1];
        int ds[8] = {a.x, a.y, a.z, a.w, b.x, b.y, b.z, b.w};
        #pragma unroll
        for (int k = 0; k < 8; k++) {
            int d = ds[k];
            if (bm_test(g_bm4, d)) {
                int s = load_src(ei_raw, 8 * i + k);
                int p = atomicAdd(&ecnt, 1);
                if (p < BUF) ebuf[p] = make_int2(s, d);
                else { int q = atomicAdd(&g_ce4, 1); if (q < CE4) g_e4[q] = make_int2(s, d); }
                if (bm_claim(g_bm3, s)) {
                    int q = atomicAdd(&ncnt, 1);
                    if (q < BUF) nbuf[q] = s;
                    else { int r = atomicAdd(&g_cl3, 1); if (r < CL3) { g_l3[r] = s; zero_row(g_agga + (size_t)s * HID); } }
                }
            }
        }
    }
    __syncthreads();
    int ec = min(ecnt, BUF), nc = min(ncnt, BUF);
    if (threadIdx.x == 0) {
        ebase = ec ? atomicAdd(&g_ce4, ec) : 0;
        nbase = nc ? atomicAdd(&g_cl3, nc) : 0;
    }
    __syncthreads();
    for (int t = threadIdx.x; t < ec; t += blockDim.x)
        if (ebase + t < CE4) g_e4[ebase + t] = ebuf[t];
    for (int t = threadIdx.x; t < nc; t += blockDim.x)
        if (nbase + t < CL3) {
            int n = nbuf[t];
            g_l3[nbase + t] = n;
            zero_row(g_agga + (size_t)n * HID);
        }
}

// fused stage-3: scan blocks: dst in bm3 -> E3, claim bm2
//                extra blocks: seed l3 -> bm2/l2
__global__ void k_scan3f(const void* __restrict__ ei_raw) {
    if (blockIdx.x >= NB_SCAN) {
        int j = (blockIdx.x - NB_SCAN) * blockDim.x + threadIdx.x;
        if (j < min(g_cl3, CL3)) {
            int n = g_l3[j];
            if (bm_claim(g_bm2, n)) {
                int p = atomicAdd(&g_cl2, 1);
                if (p < CL2) { g_l2[p] = n; g_agg1[n] = 0.f; }
            }
        }
        return;
    }
    __shared__ int2 ebuf[BUF];
    __shared__ int  nbuf[BUF];
    __shared__ int  ecnt, ncnt, ebase, nbase;
    if (threadIdx.x == 0) { ecnt = 0; ncnt = 0; }
    __syncthreads();
    int i = blockIdx.x * blockDim.x + threadIdx.x;
    if (i < NE / 8) {
        int4 a = ((const int4*)g_dstm)[2 * i];
        int4 b = ((const int4*)g_dstm)[2 * i + 1];
        int ds[8] = {a.x, a.y, a.z, a.w, b.x, b.y, b.z, b.w};
        #pragma unroll
        for (int k = 0; k < 8; k++) {
            int d = ds[k];
            if (bm_test(g_bm3, d)) {
                int s = load_src(ei_raw, 8 * i + k);
                int p = atomicAdd(&ecnt, 1);
                if (p < BUF) ebuf[p] = make_int2(s, d);
                else { int q = atomicAdd(&g_ce3, 1); if (q < CE3) g_e3[q] = make_int2(s, d); }
                if (bm_claim(g_bm2, s)) {
                    int q = atomicAdd(&ncnt, 1);
                    if (q < BUF) nbuf[q] = s;
                    else { int r = atomicAdd(&g_cl2, 1); if (r < CL2) { g_l2[r] = s; g_agg1[s] = 0.f; } }
                }
            }
        }
    }
    __syncthreads();
    int ec = min(ecnt, BUF), nc = min(ncnt, BUF);
    if (threadIdx.x == 0) {
        ebase = ec ? atomicAdd(&g_ce3, ec) : 0;
        nbase = nc ? atomicAdd(&g_cl2, nc) : 0;
    }
    __syncthreads();
    for (int t = threadIdx.x; t < ec; t += blockDim.x)
        if (ebase + t < CE3) g_e3[ebase + t] = ebuf[t];
    for (int t = threadIdx.x; t < nc; t += blockDim.x)
        if (nbase + t < CL2) {
            int n = nbuf[t];
            g_l2[nbase + t] = n;
            g_agg1[n] = 0.f;
        }
}

// P4: scan blocks: dst in bm2 -> agg1[dst] += xd[src]
//     extra blocks: CLEANUP — zero deg, bm_idx, bm4, bm3 (all dead by now)
__global__ void k_p4(const void* __restrict__ ei_raw) {
    if (blockIdx.x >= NB_SCAN) {
        int j = (blockIdx.x - NB_SCAN) * blockDim.x + threadIdx.x;
        if (j < NN) g_deg[j] = 0;
        if (j < NW) { g_bm_idx[j] = 0; g_bm4[j] = 0; g_bm3[j] = 0; }
        return;
    }
    int i = blockIdx.x * blockDim.x + threadIdx.x;
    if (i >= NE / 8) return;
    int4 a = ((const int4*)g_dstm)[2 * i];
    int4 b = ((const int4*)g_dstm)[2 * i + 1];
    int ds[8] = {a.x, a.y, a.z, a.w, b.x, b.y, b.z, b.w};
    #pragma unroll
    for (int k = 0; k < 8; k++) {
        int d = ds[k];
        if (bm_test(g_bm2, d)) {
            int s = load_src(ei_raw, 8 * i + k);
            atomicAdd(&g_agg1[d], g_xd[s]);
        }
    }
}

// layer 1+2 at S2: g2 = (relu(dinv*(agg1 + xd)*W1 + b1) @ W2) * dinv -> v2
// extra blocks: CLEANUP — zero bm2 (dead after p4)
__global__ void k_layer2(const float* __restrict__ W1,
                         const float* __restrict__ b1,
                         const float* __restrict__ W2) {
    if (blockIdx.x >= CL2 / 256) {
        int j = (blockIdx.x - CL2 / 256) * blockDim.x + threadIdx.x;
        if (j < NW) g_bm2[j] = 0;
        return;
    }
    int i = blockIdx.x * blockDim.x + threadIdx.x;
    if (i >= min(g_cl2, CL2)) return;
    int d = g_l2[i];
    float dinv = g_dinv[d];
    float pre = dinv * (g_agg1[d] + g_xd[d]);
    float h[HID];
    #pragma unroll
    for (int j = 0; j < HID; j++)
        h[j] = fmaxf(pre * __ldg(&W1[j]) + __ldg(&b1[j]), 0.f);
    float* g2 = g_v2 + (size_t)d * HID;
    #pragma unroll
    for (int j = 0; j < HID; j++) {
        float acc = 0.f;
        #pragma unroll
        for (int k = 0; k < HID; k++)
            acc = fmaf(h[k], __ldg(&W2[k * HID + j]), acc);
        g2[j] = acc * dinv;
    }
}

// edge-list aggregate: agg[dst] += gsrc[src]
__global__ void k_eagg(int which) {   // 3: E3/v2->agga ; 4: E4/v1->aggb
    int i = blockIdx.x * blockDim.x + threadIdx.x;
    int n = (which == 3) ? min(g_ce3, CE3) : min(g_ce4, CE4);
    if (i >= n) return;
    int2 sd = (which == 3) ? g_e3[i] : g_e4[i];
    const float* gs = ((which == 3) ? g_v2 : g_v1) + (size_t)sd.x * HID;
    float* ad = ((which == 3) ? g_agga : g_aggb) + (size_t)sd.y * HID;
    #pragma unroll
    for (int j = 0; j < HID; j++) atomicAdd(ad + j, gs[j]);
}

// node transform
__global__ void k_node(int which,
                       const float* __restrict__ W,
                       const float* __restrict__ b) {
    int i = blockIdx.x * blockDim.x + threadIdx.x;
    int n = (which == 3) ? min(g_cl3, CL3) : min(g_cl4, CL4);
    if (i >= n) return;
    int d = (which == 3) ? g_l3[i] : g_l4[i];
    const float* gin = ((which == 3) ? g_v2 : g_v1) + (size_t)d * HID;
    const float* ag  = ((which == 3) ? g_agga : g_aggb) + (size_t)d * HID;
    float* gout      = ((which == 3) ? g_v1 : g_v2) + (size_t)d * HID;
    float dinv = g_dinv[d];
    float h[HID];
    #pragma unroll
    for (int j = 0; j < HID; j++)
        h[j] = fmaxf(dinv * (ag[j] + gin[j]) + __ldg(&b[j]), 0.f);
    #pragma unroll
    for (int j = 0; j < HID; j++) {
        float a = 0.f;
        #pragma unroll
        for (int k = 0; k < HID; k++)
            a = fmaf(h[k], __ldg(&W[k * HID + j]), a);
        gout[j] = a * dinv;
    }
}

// final gather + counter cleanup
__global__ void k_final(const void* __restrict__ idx_raw,
                        const float* __restrict__ b4,
                        float* __restrict__ out) {
    int k = threadIdx.x;
    int n = min(g_ceidx, CE_IDX);
    int d = -1;
    if (k < NG)
        d = g_is64 ? (int)((const long long*)idx_raw)[k]
                   : ((const int*)idx_raw)[k];
    __syncthreads();
    if (k == 0) {   // cleanup for next graph replay (counts already read)
        g_ceidx = 0; g_ce4 = 0; g_ce3 = 0;
        g_cl4 = 0; g_cl3 = 0; g_cl2 = 0;
    }
    if (k >= NG) return;
    float acc8[HID];
    const float* gd = g_v2 + (size_t)d * HID;
    #pragma unroll
    for (int j = 0; j < HID; j++) acc8[j] = gd[j];
    for (int e = 0; e < n; e++) {
        int2 sd = g_eidx[e];
        if (sd.y == d) {
            const float* gs = g_v2 + (size_t)sd.x * HID;
            #pragma unroll
            for (int j = 0; j < HID; j++) acc8[j] += gs[j];
        }
    }
    float dinv = g_dinv[d];
    #pragma unroll
    for (int j = 0; j < HID; j++)
        out[k * HID + j] = dinv * acc8[j] + __ldg(&b4[j]);
}

extern "C" void kernel_launch(void* const* d_in, const int* in_sizes, int n_in,
                              void* d_out, int out_size) {
    const float* x  = (const float*)d_in[0];
    const void*  ei = d_in[1];
    const void*  idx = d_in[2];
    const float* W1 = (const float*)d_in[3];
    const float* b1 = (const float*)d_in[4];
    const float* W2 = (const float*)d_in[5];
    const float* b2 = (const float*)d_in[6];
    const float* W3 = (const float*)d_in[7];
    const float* b3 = (const float*)d_in[8];
    const float* W4 = (const float*)d_in[9];
    const float* b4 = (const float*)d_in[10];
    float* out = (float*)d_out;

    const int TB = 256;
    int nbP = (NE / 4 + TB - 1) / TB;

    k_seed0<<<1, 64>>>(ei, idx);
    k_p1<<<nbP, TB>>>(ei);
    k_scan2f<<<NB_SCAN + NB_NODE + NB_L4, TB>>>(ei, x);
    k_scan3f<<<NB_SCAN + NB_L3, TB>>>(ei);
    k_p4<<<NB_SCAN + NB_NODE, TB>>>(ei);
    k_layer2<<<CL2 / TB + NB_BM, TB>>>(W1, b1, W2);
    k_eagg<<<CE3 / TB, TB>>>(3);
    k_node<<<CL3 / TB, TB>>>(3, W3, b2);
    k_eagg<<<CE4 / TB, TB>>>(4);
    k_node<<<CL4 / TB, TB>>>(4, W4, b3);
    k_final<<<1, 64>>>(idx, b4, out);
}

// round 16
// speedup vs baseline: 1.5647x; 1.0718x over previous
#include <cuda_runtime.h>
#include <stdint.h>

#define NN 1000000
#define NE 10000000
#define HID 8
#define NG 64
#define NW 31250

#define CE_IDX 8192
#define CE4    65536
#define CE3    524288
#define CL4    8192
#define CL3    65536
#define CL2    524288
#define BUF    256

#define NB_SCAN 4883            // ceil((NE/8)/256)
#define NB_NODE 3907            // ceil(NN/256)
#define NB_L4   (CL4/256)
#define NB_L3   (CL3/256)

#define NBLK_T 592              // 148 SMs * 4 CTAs (co-resident via launch_bounds)
#define NTH_T  (NBLK_T * 256)

// ---- device scratch (zero-initialized at load; self-cleaned each run) ----
__device__ int      g_is64;
__device__ int      g_deg[NN];
__device__ float    g_dinv[NN];
__device__ float    g_xd[NN];             // x * dinv
__device__ int      g_dstm[NE];           // dst-only stream (40 MB)
__device__ float    g_agg1[NN];
__device__ float    g_agga[NN * HID];
__device__ float    g_aggb[NN * HID];
__device__ float    g_v1[NN * HID];       // g3
__device__ float    g_v2[NN * HID];       // g2 then g4
__device__ unsigned g_bm_idx[NW], g_bm4[NW], g_bm3[NW], g_bm2[NW];
__device__ int2     g_eidx[CE_IDX], g_e4[CE4], g_e3[CE3];
__device__ int      g_l4[CL4], g_l3[CL3], g_l2[CL2];
__device__ int      g_ceidx, g_ce4, g_ce3, g_cl4, g_cl3, g_cl2;

// software grid barrier (generation-based; replay-safe)
__device__ volatile int g_bar_cnt;
__device__ volatile int g_bar_gen;

__device__ __forceinline__ bool bm_test(const unsigned* bm, int i) {
    return (bm[i >> 5] >> (i & 31)) & 1u;
}
__device__ __forceinline__ bool bm_claim(unsigned* bm, int i) {
    unsigned old = atomicOr(&bm[i >> 5], 1u << (i & 31));
    return !((old >> (i & 31)) & 1u);
}
__device__ __forceinline__ int load_src(const void* ei_raw, int e) {
    return g_is64 ? (int)((const long long*)ei_raw)[e]
                  : ((const int*)ei_raw)[e];
}
__device__ __forceinline__ void zero_row(float* p) {
    float4 z = make_float4(0.f, 0.f, 0.f, 0.f);
    ((float4*)p)[0] = z; ((float4*)p)[1] = z;
}
__device__ __forceinline__ void gbar() {
    __syncthreads();
    if (threadIdx.x == 0) {
        int gen = g_bar_gen;
        __threadfence();
        if (atomicAdd((int*)&g_bar_cnt, 1) == NBLK_T - 1) {
            g_bar_cnt = 0;
            __threadfence();
            g_bar_gen = gen + 1;
        } else {
            while (g_bar_gen == gen) { }
        }
        __threadfence();
    }
    __syncthreads();
}

// seed: dtype detect then mark indices
__global__ void k_seed0(const void* __restrict__ ei_raw,
                        const void* __restrict__ idx_raw) {
    __shared__ int s64;
    if (threadIdx.x == 0) {
        const int* w = (const int*)ei_raw;
        int zeros = 0;
        for (int k = 1; k < 128; k += 2)
            if (w[k] == 0) zeros++;
        s64 = (zeros >= 48) ? 1 : 0;
        g_is64 = s64;
    }
    __syncthreads();
    int k = threadIdx.x;
    if (k >= NG) return;
    int n = s64 ? (int)((const long long*)idx_raw)[k]
                : ((const int*)idx_raw)[k];
    bm_claim(g_bm_idx, n);
    if (bm_claim(g_bm4, n)) {
        int p = atomicAdd(&g_cl4, 1);
        g_l4[p] = n;
        zero_row(g_aggb + (size_t)n * HID);
    }
}

// P1: 4 edges/thread; dst stream + degree + E_idx capture + S4 claims
__global__ void k_p1(const void* __restrict__ ei_raw) {
    __shared__ int2 ebuf[BUF];
    __shared__ int  nbuf[BUF];
    __shared__ int  ecnt, ncnt, ebase, nbase;
    if (threadIdx.x == 0) { ecnt = 0; ncnt = 0; }
    __syncthreads();
    int i = blockIdx.x * blockDim.x + threadIdx.x;
    if (i < NE / 4) {
        int d[4];
        if (g_is64) {
            longlong2 a = ((const longlong2*)ei_raw)[NE / 2 + 2 * i];
            longlong2 b = ((const longlong2*)ei_raw)[NE / 2 + 2 * i + 1];
            d[0] = (int)a.x; d[1] = (int)a.y; d[2] = (int)b.x; d[3] = (int)b.y;
        } else {
            int4 a = ((const int4*)ei_raw)[NE / 4 + i];
            d[0] = a.x; d[1] = a.y; d[2] = a.z; d[3] = a.w;
        }
        ((int4*)g_dstm)[i] = make_int4(d[0], d[1], d[2], d[3]);
        #pragma unroll
        for (int k = 0; k < 4; k++) atomicAdd(&g_deg[d[k]], 1);
        #pragma unroll
        for (int k = 0; k < 4; k++) {
            if (bm_test(g_bm_idx, d[k])) {
                int s = load_src(ei_raw, 4 * i + k);
                int p = atomicAdd(&ecnt, 1);
                if (p < BUF) ebuf[p] = make_int2(s, d[k]);
                else { int q = atomicAdd(&g_ceidx, 1); if (q < CE_IDX) g_eidx[q] = make_int2(s, d[k]); }
                if (bm_claim(g_bm4, s)) {
                    int q = atomicAdd(&ncnt, 1);
                    if (q < BUF) nbuf[q] = s;
                    else { int r = atomicAdd(&g_cl4, 1); if (r < CL4) { g_l4[r] = s; zero_row(g_aggb + (size_t)s * HID); } }
                }
            }
        }
    }
    __syncthreads();
    int ec = min(ecnt, BUF), nc = min(ncnt, BUF);
    if (threadIdx.x == 0) {
        ebase = ec ? atomicAdd(&g_ceidx, ec) : 0;
        nbase = nc ? atomicAdd(&g_cl4, nc) : 0;
    }
    __syncthreads();
    for (int t = threadIdx.x; t < ec; t += blockDim.x)
        if (ebase + t < CE_IDX) g_eidx[ebase + t] = ebuf[t];
    for (int t = threadIdx.x; t < nc; t += blockDim.x)
        if (nbase + t < CL4) {
            int n = nbuf[t];
            g_l4[nbase + t] = n;
            zero_row(g_aggb + (size_t)n * HID);
        }
}

// fused stage-2: scan blocks: dst in bm4 -> E4, claim bm3
//                extra blocks: dinv+xd ; seed l4 -> bm3/l3
__global__ void k_scan2f(const void* __restrict__ ei_raw,
                         const float* __restrict__ x) {
    if (blockIdx.x >= NB_SCAN) {
        int rb = blockIdx.x - NB_SCAN;
        if (rb < NB_NODE) {
            int n = rb * blockDim.x + threadIdx.x;
            if (n < NN) {
                float dinv = rsqrtf((float)g_deg[n] + 1.0f);
                g_dinv[n] = dinv;
                g_xd[n] = x[n] * dinv;
            }
        } else {
            int j = (rb - NB_NODE) * blockDim.x + threadIdx.x;
            if (j < min(g_cl4, CL4)) {
                int n = g_l4[j];
                if (bm_claim(g_bm3, n)) {
                    int p = atomicAdd(&g_cl3, 1);
                    if (p < CL3) { g_l3[p] = n; zero_row(g_agga + (size_t)n * HID); }
                }
            }
        }
        return;
    }
    __shared__ int2 ebuf[BUF];
    __shared__ int  nbuf[BUF];
    __shared__ int  ecnt, ncnt, ebase, nbase;
    if (threadIdx.x == 0) { ecnt = 0; ncnt = 0; }
    __syncthreads();
    int i = blockIdx.x * blockDim.x + threadIdx.x;
    if (i < NE / 8) {
        int4 a = ((const int4*)g_dstm)[2 * i];
        int4 b = ((const int4*)g_dstm)[2 * i + 1];
        int ds[8] = {a.x, a.y, a.z, a.w, b.x, b.y, b.z, b.w};
        #pragma unroll
        for (int k = 0; k < 8; k++) {
            int d = ds[k];
            if (bm_test(g_bm4, d)) {
                int s = load_src(ei_raw, 8 * i + k);
                int p = atomicAdd(&ecnt, 1);
                if (p < BUF) ebuf[p] = make_int2(s, d);
                else { int q = atomicAdd(&g_ce4, 1); if (q < CE4) g_e4[q] = make_int2(s, d); }
                if (bm_claim(g_bm3, s)) {
                    int q = atomicAdd(&ncnt, 1);
                    if (q < BUF) nbuf[q] = s;
                    else { int r = atomicAdd(&g_cl3, 1); if (r < CL3) { g_l3[r] = s; zero_row(g_agga + (size_t)s * HID); } }
                }
            }
        }
    }
    __syncthreads();
    int ec = min(ecnt, BUF), nc = min(ncnt, BUF);
    if (threadIdx.x == 0) {
        ebase = ec ? atomicAdd(&g_ce4, ec) : 0;
        nbase = nc ? atomicAdd(&g_cl3, nc) : 0;
    }
    __syncthreads();
    for (int t = threadIdx.x; t < ec; t += blockDim.x)
        if (ebase + t < CE4) g_e4[ebase + t] = ebuf[t];
    for (int t = threadIdx.x; t < nc; t += blockDim.x)
        if (nbase + t < CL3) {
            int n = nbuf[t];
            g_l3[nbase + t] = n;
            zero_row(g_agga + (size_t)n * HID);
        }
}

// fused stage-3: scan blocks: dst in bm3 -> E3, claim bm2
//                extra blocks: seed l3 -> bm2/l2
__global__ void k_scan3f(const void* __restrict__ ei_raw) {
    if (blockIdx.x >= NB_SCAN) {
        int j = (blockIdx.x - NB_SCAN) * blockDim.x + threadIdx.x;
        if (j < min(g_cl3, CL3)) {
            int n = g_l3[j];
            if (bm_claim(g_bm2, n)) {
                int p = atomicAdd(&g_cl2, 1);
                if (p < CL2) { g_l2[p] = n; g_agg1[n] = 0.f; }
            }
        }
        return;
    }
    __shared__ int2 ebuf[BUF];
    __shared__ int  nbuf[BUF];
    __shared__ int  ecnt, ncnt, ebase, nbase;
    if (threadIdx.x == 0) { ecnt = 0; ncnt = 0; }
    __syncthreads();
    int i = blockIdx.x * blockDim.x + threadIdx.x;
    if (i < NE / 8) {
        int4 a = ((const int4*)g_dstm)[2 * i];
        int4 b = ((const int4*)g_dstm)[2 * i + 1];
        int ds[8] = {a.x, a.y, a.z, a.w, b.x, b.y, b.z, b.w};
        #pragma unroll
        for (int k = 0; k < 8; k++) {
            int d = ds[k];
            if (bm_test(g_bm3, d)) {
                int s = load_src(ei_raw, 8 * i + k);
                int p = atomicAdd(&ecnt, 1);
                if (p < BUF) ebuf[p] = make_int2(s, d);
                else { int q = atomicAdd(&g_ce3, 1); if (q < CE3) g_e3[q] = make_int2(s, d); }
                if (bm_claim(g_bm2, s)) {
                    int q = atomicAdd(&ncnt, 1);
                    if (q < BUF) nbuf[q] = s;
                    else { int r = atomicAdd(&g_cl2, 1); if (r < CL2) { g_l2[r] = s; g_agg1[s] = 0.f; } }
                }
            }
        }
    }
    __syncthreads();
    int ec = min(ecnt, BUF), nc = min(ncnt, BUF);
    if (threadIdx.x == 0) {
        ebase = ec ? atomicAdd(&g_ce3, ec) : 0;
        nbase = nc ? atomicAdd(&g_cl2, nc) : 0;
    }
    __syncthreads();
    for (int t = threadIdx.x; t < ec; t += blockDim.x)
        if (ebase + t < CE3) g_e3[ebase + t] = ebuf[t];
    for (int t = threadIdx.x; t < nc; t += blockDim.x)
        if (nbase + t < CL2) {
            int n = nbuf[t];
            g_l2[nbase + t] = n;
            g_agg1[n] = 0.f;
        }
}

// P4: scan blocks: dst in bm2 -> agg1[dst] += xd[src]
//     extra blocks: CLEANUP — zero deg, bm_idx, bm4, bm3
__global__ void k_p4(const void* __restrict__ ei_raw) {
    if (blockIdx.x >= NB_SCAN) {
        int j = (blockIdx.x - NB_SCAN) * blockDim.x + threadIdx.x;
        if (j < NN) g_deg[j] = 0;
        if (j < NW) { g_bm_idx[j] = 0; g_bm4[j] = 0; g_bm3[j] = 0; }
        return;
    }
    int i = blockIdx.x * blockDim.x + threadIdx.x;
    if (i >= NE / 8) return;
    int4 a = ((const int4*)g_dstm)[2 * i];
    int4 b = ((const int4*)g_dstm)[2 * i + 1];
    int ds[8] = {a.x, a.y, a.z, a.w, b.x, b.y, b.z, b.w};
    #pragma unroll
    for (int k = 0; k < 8; k++) {
        int d = ds[k];
        if (bm_test(g_bm2, d)) {
            int s = load_src(ei_raw, 8 * i + k);
            atomicAdd(&g_agg1[d], g_xd[s]);
        }
    }
}

// fused tail: layer2 -> eagg3 -> node3 -> eagg4 -> node4 -> final
// 592 CTAs (4/SM guaranteed co-resident) with grid barriers between phases.
__global__ void __launch_bounds__(256, 4) k_tail(
    const void* __restrict__ idx_raw,
    const float* __restrict__ W1, const float* __restrict__ b1,
    const float* __restrict__ W2, const float* __restrict__ b2,
    const float* __restrict__ W3, const float* __restrict__ b3,
    const float* __restrict__ W4, const float* __restrict__ b4,
    float* __restrict__ out)
{
    const int gid = blockIdx.x * 256 + threadIdx.x;

    // phase A: layer 1+2 at l2 -> v2 ; plus bm2 cleanup (dead after p4)
    {
        int n2 = min(g_cl2, CL2);
        for (int i = gid; i < n2; i += NTH_T) {
            int d = g_l2[i];
            float dinv = g_dinv[d];
            float pre = dinv * (g_agg1[d] + g_xd[d]);
            float h[HID];
            #pragma unroll
            for (int j = 0; j < HID; j++)
                h[j] = fmaxf(pre * __ldg(&W1[j]) + __ldg(&b1[j]), 0.f);
            float* g2 = g_v2 + (size_t)d * HID;
            #pragma unroll
            for (int j = 0; j < HID; j++) {
                float acc = 0.f;
                #pragma unroll
                for (int k = 0; k < HID; k++)
                    acc = fmaf(h[k], __ldg(&W2[k * HID + j]), acc);
                g2[j] = acc * dinv;
            }
        }
        for (int j = gid; j < NW; j += NTH_T) g_bm2[j] = 0;
    }
    gbar();

    // phase B: eagg3 — agga[dst] += v2[src] over E3
    {
        int ne3 = min(g_ce3, CE3);
        for (int i = gid; i < ne3; i += NTH_T) {
            int2 sd = g_e3[i];
            const float* gs = g_v2 + (size_t)sd.x * HID;
            float* ad = g_agga + (size_t)sd.y * HID;
            #pragma unroll
            for (int j = 0; j < HID; j++) atomicAdd(ad + j, gs[j]);
        }
    }
    gbar();

    // phase C: node3 at l3 -> v1
    {
        int n3 = min(g_cl3, CL3);
        for (int i = gid; i < n3; i += NTH_T) {
            int d = g_l3[i];
            float dinv = g_dinv[d];
            const float* gin = g_v2 + (size_t)d * HID;
            const float* ag  = g_agga + (size_t)d * HID;
            float* go        = g_v1 + (size_t)d * HID;
            float h[HID];
            #pragma unroll
            for (int j = 0; j < HID; j++)
                h[j] = fmaxf(dinv * (ag[j] + gin[j]) + __ldg(&b2[j]), 0.f);
            #pragma unroll
            for (int j = 0; j < HID; j++) {
                float acc = 0.f;
                #pragma unroll
                for (int k = 0; k < HID; k++)
                    acc = fmaf(h[k], __ldg(&W3[k * HID + j]), acc);
                go[j] = acc * dinv;
            }
        }
    }
    gbar();

    // phase D: eagg4 — aggb[dst] += v1[src] over E4
    {
        int ne4 = min(g_ce4, CE4);
        for (int i = gid; i < ne4; i += NTH_T) {
            int2 sd = g_e4[i];
            const float* gs = g_v1 + (size_t)sd.x * HID;
            float* ad = g_aggb + (size_t)sd.y * HID;
            #pragma unroll
            for (int j = 0; j < HID; j++) atomicAdd(ad + j, gs[j]);
        }
    }
    gbar();

    // phase E: node4 at l4 -> v2
    {
        int n4 = min(g_cl4, CL4);
        for (int i = gid; i < n4; i += NTH_T) {
            int d = g_l4[i];
            float dinv = g_dinv[d];
            const float* gin = g_v1 + (size_t)d * HID;
            const float* ag  = g_aggb + (size_t)d * HID;
            float* go        = g_v2 + (size_t)d * HID;
            float h[HID];
            #pragma unroll
            for (int j = 0; j < HID; j++)
                h[j] = fmaxf(dinv * (ag[j] + gin[j]) + __ldg(&b3[j]), 0.f);
            #pragma unroll
            for (int j = 0; j < HID; j++) {
                float acc = 0.f;
                #pragma unroll
                for (int k = 0; k < HID; k++)
                    acc = fmaf(h[k], __ldg(&W4[k * HID + j]), acc);
                go[j] = acc * dinv;
            }
        }
    }
    gbar();

    // phase F: final gather (block 0) + counter cleanup
    if (blockIdx.x == 0) {
        int k = threadIdx.x;
        int n = min(g_ceidx, CE_IDX);
        int d = -1;
        if (k < NG)
            d = g_is64 ? (int)((const long long*)idx_raw)[k]
                       : ((const int*)idx_raw)[k];
        __syncthreads();
        if (k == 0) {   // counts consumed; reset for next replay
            g_ceidx = 0; g_ce4 = 0; g_ce3 = 0;
            g_cl4 = 0; g_cl3 = 0; g_cl2 = 0;
        }
        if (k < NG) {
            float acc8[HID];
            const float* gd = g_v2 + (size_t)d * HID;
            #pragma unroll
            for (int j = 0; j < HID; j++) acc8[j] = gd[j];
            for (int e = 0; e < n; e++) {
                int2 sd = g_eidx[e];
                if (sd.y == d) {
                    const float* gs = g_v2 + (size_t)sd.x * HID;
                    #pragma unroll
                    for (int j = 0; j < HID; j++) acc8[j] += gs[j];
                }
            }
            float dinv = g_dinv[d];
            #pragma unroll
            for (int j = 0; j < HID; j++)
                out[k * HID + j] = dinv * acc8[j] + __ldg(&b4[j]);
        }
    }
}

extern "C" void kernel_launch(void* const* d_in, const int* in_sizes, int n_in,
                              void* d_out, int out_size) {
    const float* x  = (const float*)d_in[0];
    const void*  ei = d_in[1];
    const void*  idx = d_in[2];
    const float* W1 = (const float*)d_in[3];
    const float* b1 = (const float*)d_in[4];
    const float* W2 = (const float*)d_in[5];
    const float* b2 = (const float*)d_in[6];
    const float* W3 = (const float*)d_in[7];
    const float* b3 = (const float*)d_in[8];
    const float* W4 = (const float*)d_in[9];
    const float* b4 = (const float*)d_in[10];
    float* out = (float*)d_out;

    const int TB = 256;
    int nbP = (NE / 4 + TB - 1) / TB;

    k_seed0<<<1, 64>>>(ei, idx);
    k_p1<<<nbP, TB>>>(ei);
    k_scan2f<<<NB_SCAN + NB_NODE + NB_L4, TB>>>(ei, x);
    k_scan3f<<<NB_SCAN + NB_L3, TB>>>(ei);
    k_p4<<<NB_SCAN + NB_NODE, TB>>>(ei);
    k_tail<<<NBLK_T, TB>>>(idx, W1, b1, W2, b2, W3, b3, W4, b4, out);
}